// round 15
// baseline (speedup 1.0000x reference)
#include <cuda_runtime.h>
#include <cuda_bf16.h>
#include <math.h>
#include <stdint.h>

#define BATCH 4096
#define DIM   1024
#define NROWS 30

#define NGEMM  152            // CTAs that continue GEMM after round 1
#define GRID   304            // 2 CTAs/SM x 152 SMs, one wave
#define NSTRM  (GRID - NGEMM) // streamer CTAs (steal ONE tile, then epilogue)
#define NTILES 512            // 32 m-blocks x 16 n-blocks
#define FSMEM  (65536 + 128)  // GEMM A/B buffers + steal slots
#define NCHUNK 786432         // float8 chunks to convert (X, Wb, Wc)

// ---------------------------------------------------------------------------
// Scratch
// ---------------------------------------------------------------------------
__device__ __align__(16) float g_embs[(size_t)BATCH * 2048];
__device__ __align__(16) __nv_bfloat16 g_xbf[(size_t)BATCH * DIM];
__device__ __align__(16) __nv_bfloat16 g_wbf[(size_t)2048 * DIM];
__device__ __align__(16) float g_vcancel[DIM];
__device__ float g_scancel;
__device__ int g_tile_ctr;
__device__ int g_batch_ctr;
__device__ int g_mdone[32];
__device__ int g_conv_done;

__device__ __forceinline__ float dot4(float4 a, float4 b) {
    return a.x * b.x + a.y * b.y + a.z * b.z + a.w * b.w;
}
__device__ __forceinline__ void cp16(uint32_t dst, const void* src) {
    asm volatile("cp.async.cg.shared.global [%0], [%1], 16;\n" :: "r"(dst), "l"(src));
}
__device__ __forceinline__ void cp_commit() {
    asm volatile("cp.async.commit_group;\n");
}
template <int N>
__device__ __forceinline__ void cp_wait() {
    asm volatile("cp.async.wait_group %0;\n" :: "n"(N));
}
__device__ __forceinline__ void ldmx4(uint32_t* r, uint32_t addr) {
    asm volatile("ldmatrix.sync.aligned.m8n8.x4.shared.b16 {%0,%1,%2,%3}, [%4];"
                 : "=r"(r[0]), "=r"(r[1]), "=r"(r[2]), "=r"(r[3]) : "r"(addr));
}
#define MMA_BF16(C, A, B0, B1)                                                 \
    asm volatile(                                                              \
        "mma.sync.aligned.m16n8k16.row.col.f32.bf16.bf16.f32 "                 \
        "{%0,%1,%2,%3}, {%4,%5,%6,%7}, {%8,%9}, {%0,%1,%2,%3};"                \
        : "+f"((C)[0]), "+f"((C)[1]), "+f"((C)[2]), "+f"((C)[3])               \
        : "r"((A)[0]), "r"((A)[1]), "r"((A)[2]), "r"((A)[3]),                  \
          "r"(B0), "r"(B1))

// ---------------------------------------------------------------------------
// Kernel 0: init counters + zero g_vcancel + compute g_scancel.  1 x 256.
// ---------------------------------------------------------------------------
__global__ void init_kernel(const float* __restrict__ cb,
                            const float* __restrict__ gw) {
    __shared__ float red[8];
    const int t = threadIdx.x, w = t >> 5, l = t & 31;
    ((float4*)g_vcancel)[t] = make_float4(0.f, 0.f, 0.f, 0.f);
    if (t < 32) g_mdone[t] = 0;
    if (t == 32) g_tile_ctr = 0;
    if (t == 33) g_batch_ctr = 0;
    if (t == 34) g_conv_done = 0;
    float4 c = ((const float4*)cb)[t];
    float4 g = ((const float4*)gw)[t];
    float p = dot4(c, g);
    #pragma unroll
    for (int o = 16; o > 0; o >>= 1) p += __shfl_down_sync(0xffffffffu, p, o);
    if (l == 0) red[w] = p;
    __syncthreads();
    if (t == 0) {
        float s = 0.f;
        #pragma unroll
        for (int j = 0; j < 8; j++) s += red[j];
        g_scancel = s;
    }
}

// ---------------------------------------------------------------------------
// GEMM tile, 512 threads, warp tile 32x32 (R9/R10 version, 64 regs).
// ---------------------------------------------------------------------------
__device__ __forceinline__ void gemm_tile(int m0, int n0,
                                          uint32_t baseA, uint32_t baseB,
                                          const float* __restrict__ bb,
                                          const float* __restrict__ bch) {
    const int t = threadIdx.x;
    const int warp = t >> 5, lane = t & 31;
    const int wm = warp >> 2, wn = warp & 3;
    const int g = lane >> 2, tg = lane & 3;
    const int q = lane >> 3, r8 = lane & 7;
    const int qm = (q & 1) * 8 + r8;
    const int qk = (q >> 1) * 8;

    float acc[2][4][4];
    #pragma unroll
    for (int mt = 0; mt < 2; mt++)
        #pragma unroll
        for (int nt = 0; nt < 4; nt++)
            #pragma unroll
            for (int j = 0; j < 4; j++) acc[mt][nt][j] = 0.f;

    int lm[2], lc[2];
    #pragma unroll
    for (int i = 0; i < 2; i++) {
        int chunk = t + 512 * i;
        lm[i] = chunk >> 3;
        lc[i] = chunk & 7;
    }

    auto issue = [&](int s) {
        const int kb = s * 64;
        const uint32_t bo = (s & 1) * 16384;
        #pragma unroll
        for (int i = 0; i < 2; i++) {
            const int m = lm[i], c = lc[i];
            const int pc = c ^ (m & 7);
            cp16(baseA + bo + m * 128 + pc * 16,
                 g_xbf + (size_t)(m0 + m) * DIM + kb + c * 8);
            cp16(baseB + bo + m * 128 + pc * 16,
                 g_wbf + (size_t)(n0 + m) * DIM + kb + c * 8);
        }
        cp_commit();
    };

    issue(0);

    for (int s = 0; s < 16; s++) {
        __syncthreads();
        if (s < 15) { issue(s + 1); cp_wait<1>(); }
        else        { cp_wait<0>(); }
        __syncthreads();

        const uint32_t bo = (s & 1) * 16384;
        #pragma unroll
        for (int ks = 0; ks < 4; ks++) {
            const int kc = ks * 16 + qk;
            uint32_t af[2][4];
            #pragma unroll
            for (int mt = 0; mt < 2; mt++) {
                const int m = wm * 32 + mt * 16 + qm;
                ldmx4(af[mt], baseA + bo + m * 128 + (((kc >> 3) ^ (m & 7)) * 16));
            }
            uint32_t b0[4], b1[4];
            #pragma unroll
            for (int ntp = 0; ntp < 2; ntp++) {
                const int n = wn * 32 + ntp * 16 + qm;
                uint32_t r[4];
                ldmx4(r, baseB + bo + n * 128 + (((kc >> 3) ^ (n & 7)) * 16));
                b0[2 * ntp] = r[0]; b0[2 * ntp + 1] = r[1];
                b1[2 * ntp] = r[2]; b1[2 * ntp + 1] = r[3];
            }
            #pragma unroll
            for (int mt = 0; mt < 2; mt++)
                #pragma unroll
                for (int nt = 0; nt < 4; nt++)
                    MMA_BF16(acc[mt][nt], af[mt], b0[nt], b1[nt]);
        }
    }

    const float* bsel = (n0 < 1024) ? (bb + n0) : (bch + (n0 - 1024));
    #pragma unroll
    for (int mt = 0; mt < 2; mt++) {
        #pragma unroll
        for (int nt = 0; nt < 4; nt++) {
            const int row = m0 + wm * 32 + mt * 16 + g;
            const int col = wn * 32 + nt * 8 + 2 * tg;
            const float c0 = bsel[col], c1 = bsel[col + 1];
            float2 v01 = make_float2(acc[mt][nt][0] + c0, acc[mt][nt][1] + c1);
            float2 v23 = make_float2(acc[mt][nt][2] + c0, acc[mt][nt][3] + c1);
            *(float2*)&g_embs[(size_t)row * 2048 + n0 + col] = v01;
            *(float2*)&g_embs[(size_t)(row + 8) * 2048 + n0 + col] = v23;
        }
    }
}

// ---------------------------------------------------------------------------
// Epilogue body for one batch row, executed by a 256-thread half (t in 0..255)
// with its own smem bank `sm`. Embeddings in SMEM, ONE row per warp (measured
// optimum; wider variants hit the register cliff).
// ---------------------------------------------------------------------------
__device__ __forceinline__ void epi_row(
        int b, char* sm, int t,
        const float* __restrict__ X, const float* __restrict__ table,
        const float* __restrict__ nf, const float* __restrict__ res,
        const float* __restrict__ goalW, const float* __restrict__ goalb,
        const float* __restrict__ chgW, const float* __restrict__ chgb,
        const float* __restrict__ ccgW, const float* __restrict__ ccgb,
        float* __restrict__ out) {
    const int w = t >> 5, l = t & 31;

    float4* sbe = (float4*)sm;
    float4* sce = (float4*)(sm + 4096);
    float (*red)[9] = (float(*)[9])(sm + 8192);
    float* sdots = (float*)(sm + 8480);
    float* slb = (float*)(sm + 8516);
    float* slc = (float*)(sm + 8644);
    float* spb = (float*)(sm + 8772);
    float* spc = (float*)(sm + 8900);
    float* sc  = (float*)(sm + 9028);

    const float* be  = g_embs + (size_t)b * 2048;
    const float* ce  = be + 1024;
    const float* xb  = X   + (size_t)b * DIM;
    const float* nfb = nf  + (size_t)b * DIM;
    const float* rb  = res + (size_t)b * DIM;

    // ---- phase 1: nine 1024-length dots + stage embs to smem ----
    float p[9];
    {
        const int i0 = t * 4;
        float4 bv = *(const float4*)(be + i0);
        float4 cv = *(const float4*)(ce + i0);
        sbe[t] = bv;
        sce[t] = cv;
        float4 xv = *(const float4*)(xb + i0);
        float4 nv = *(const float4*)(nfb + i0);
        float4 rv = *(const float4*)(rb + i0);
        float4 g0 = *(const float4*)(goalW + i0);
        float4 g1 = *(const float4*)(goalW + 1024 + i0);
        float4 g2 = *(const float4*)(goalW + 2048 + i0);
        float4 cl = *(const float4*)(chgW + i0);
        float4 ch = *(const float4*)(chgW + 1024 + i0);
        float4 kh = *(const float4*)(ccgW + 1024 + i0);
        float4 vc = *(const float4*)(g_vcancel + i0);
        p[0] = dot4(bv, nv);
        p[1] = dot4(cv, nv);
        p[2] = dot4(cv, cl);
        p[3] = dot4(rv, ch);
        p[4] = dot4(xv, vc);
        p[5] = dot4(rv, kh);
        p[6] = dot4(xv, g0);
        p[7] = dot4(xv, g1);
        p[8] = dot4(xv, g2);
    }
    #pragma unroll
    for (int j = 0; j < 9; j++) {
        #pragma unroll
        for (int o = 16; o > 0; o >>= 1)
            p[j] += __shfl_down_sync(0xffffffffu, p[j], o);
    }
    if (l == 0) {
        #pragma unroll
        for (int j = 0; j < 9; j++) red[w][j] = p[j];
    }
    __syncthreads();
    if (t < 9) {
        float s = 0.f;
        #pragma unroll
        for (int ww = 0; ww < 8; ww++) s += red[ww][t];
        sdots[t] = s;
    }

    // ---- phase 2: table logits, 1 row per warp, dual dot ----
    for (int r = w; r < NROWS; r += 8) {
        const float4* t4 = (const float4*)(table + ((size_t)b * NROWS + r) * DIM);
        float ab = 0.f, ac = 0.f;
        #pragma unroll
        for (int j = 0; j < 8; j++) {
            float4 tv = t4[j * 32 + l];
            ab += dot4(tv, sbe[j * 32 + l]);
            ac += dot4(tv, sce[j * 32 + l]);
        }
        #pragma unroll
        for (int o = 16; o > 0; o >>= 1) {
            ab += __shfl_down_sync(0xffffffffu, ab, o);
            ac += __shfl_down_sync(0xffffffffu, ac, o);
        }
        if (l == 0) {
            slb[r + 1] = ab * 0.03125f;
            slc[r + 1] = ac * 0.03125f;
        }
    }
    __syncthreads();

    // ---- phase 3a: scalars ----
    if (t == 0) {
        slb[0] = sdots[0] * 0.03125f;
        slc[0] = sdots[1] * 0.03125f;
        float l0 = sdots[6] + goalb[0];
        float l1 = sdots[7] + goalb[1];
        float l2 = sdots[8] + goalb[2];
        float mx = fmaxf(l0, fmaxf(l1, l2));
        float e0 = expf(l0 - mx), e1 = expf(l1 - mx), e2 = expf(l2 - mx);
        float inv = 1.f / (e0 + e1 + e2);
        float bg = e0 * inv, chg = e1 * inv, cang = e2 * inv;
        float change_prob = 1.f / (1.f + expf(-(sdots[2] + sdots[3] + chgb[0])));
        float cancel_prob = 1.f / (1.f + expf(-(sdots[4] + sdots[5] + g_scancel + ccgb[0])));
        sc[0] = bg;
        sc[1] = chg * change_prob;
        sc[2] = cang * cancel_prob;
        sc[3] = cang * (1.f - cancel_prob) + chg * (1.f - change_prob);
    }
    __syncthreads();

    // ---- phase 3b: two 31-way softmaxes ----
    if (w < 2) {
        float* sl = w ? slc : slb;
        float* sp = w ? spc : spb;
        float v = (l < 31) ? sl[l] : -1e30f;
        float mx = v;
        #pragma unroll
        for (int o = 16; o > 0; o >>= 1)
            mx = fmaxf(mx, __shfl_xor_sync(0xffffffffu, mx, o));
        float e = (l < 31) ? expf(v - mx) : 0.f;
        float s = e;
        #pragma unroll
        for (int o = 16; o > 0; o >>= 1)
            s += __shfl_xor_sync(0xffffffffu, s, o);
        if (l < 31) sp[l] = e / s;
    }
    __syncthreads();

    // ---- phase 3c: final 63 outputs ----
    if (t < 63) {
        float o;
        if (t == 0)       o = sc[0] * spb[0] + sc[1] * spc[0];
        else if (t == 1)  o = sc[2];
        else if (t == 2)  o = sc[3];
        else if (t < 33)  o = sc[0] * spb[t - 2];
        else              o = sc[1] * spc[t - 32];
        out[(size_t)b * 63 + t] = o;
    }
}

// ---------------------------------------------------------------------------
// FUSED persistent kernel, round-1-everywhere scheduling:
//   all 304 CTAs: conv chunk (streamers also do cancel matvec first)
//                 -> barrier(304) -> steal GEMM tiles.
//   Streamers (bid>=152) defect to the epilogue after ONE tile; GEMM CTAs
//   (bid<152) keep stealing until tiles are gone, then join the epilogue.
// Removes the ~35us streamer startup idle of the previous schedule.
// ---------------------------------------------------------------------------
__global__ void __launch_bounds__(512, 2)
fused_kernel(const float* __restrict__ X, const float* __restrict__ table,
             const float* __restrict__ nf, const float* __restrict__ res,
             const float* __restrict__ goalW, const float* __restrict__ goalb,
             const float* __restrict__ bb, const float* __restrict__ bch,
             const float* __restrict__ chgW, const float* __restrict__ chgb,
             const float* __restrict__ ccgW, const float* __restrict__ ccgb,
             const float* __restrict__ Wb_f32, const float* __restrict__ Wc_f32,
             const float* __restrict__ ccW,
             float* __restrict__ out) {
    extern __shared__ char smem[];
    const uint32_t baseA = (uint32_t)__cvta_generic_to_shared(smem);
    const uint32_t baseB = baseA + 32768;
    volatile int* steal = (volatile int*)(smem + 65536);

    const int t = threadIdx.x;
    const int bid = blockIdx.x;
    const bool is_streamer = (bid >= NGEMM);

    // ---- streamers: folded cancel matvec (64 units of 512k x 32i) ----
    if (is_streamer) {
        const int e = bid - NGEMM;
        if (e < 64) {
            const int k  = (e & 1) * 512 + t;
            const int i0 = (e >> 1) * 32;
            float acc = 0.f;
            #pragma unroll
            for (int j = 0; j < 32; j++)
                acc += ccW[(size_t)(i0 + j) * DIM + k] * __ldg(ccgW + i0 + j);
            atomicAdd(&g_vcancel[k], acc);
        }
    }

    // ---- conv_bf16: grid-stride over ALL 304 CTAs ----
    for (int c = bid * 512 + t; c < NCHUNK; c += GRID * 512) {
        const float* src;
        __nv_bfloat16* dst;
        size_t off;
        if (c < 524288)      { src = X;      dst = g_xbf;            off = (size_t)c * 8; }
        else if (c < 655360) { src = Wb_f32; dst = g_wbf;            off = (size_t)(c - 524288) * 8; }
        else                 { src = Wc_f32; dst = g_wbf + (1u<<20); off = (size_t)(c - 655360) * 8; }
        float4 a0 = *(const float4*)(src + off);
        float4 a1 = *(const float4*)(src + off + 4);
        __nv_bfloat162 h0 = __floats2bfloat162_rn(a0.x, a0.y);
        __nv_bfloat162 h1 = __floats2bfloat162_rn(a0.z, a0.w);
        __nv_bfloat162 h2 = __floats2bfloat162_rn(a1.x, a1.y);
        __nv_bfloat162 h3 = __floats2bfloat162_rn(a1.z, a1.w);
        uint4 o;
        o.x = *(uint32_t*)&h0; o.y = *(uint32_t*)&h1;
        o.z = *(uint32_t*)&h2; o.w = *(uint32_t*)&h3;
        *(uint4*)(dst + off) = o;
    }
    __threadfence();
    __syncthreads();
    if (t == 0) {
        atomicAdd(&g_conv_done, 1);
        while (atomicAdd(&g_conv_done, 0) < GRID) __nanosleep(64);
    }
    __syncthreads();
    __threadfence();   // acquire: g_xbf/g_wbf/g_vcancel complete everywhere

    // ---- GEMM tile stealing; streamers take exactly ONE tile ----
    for (;;) {
        if (t == 0) steal[0] = atomicAdd(&g_tile_ctr, 1);
        __syncthreads();
        const int tile = steal[0];
        if (tile >= NTILES) break;
        const int m = tile >> 4, n = tile & 15;
        gemm_tile(m * 128, n * 128, baseA, baseB, bb, bch);
        __threadfence();
        __syncthreads();
        if (t == 0) atomicAdd(&g_mdone[m], 1);
        if (is_streamer) break;   // one tile, then go stream
    }
    __syncthreads();

    // ---- epilogue phase: 2 rows per iteration (halves) ----
    for (;;) {
        if (t == 0) {
            int b0 = atomicAdd(&g_batch_ctr, 2);
            steal[1] = b0;
            if (b0 < BATCH) {
                const int m = b0 >> 7;
                while (atomicAdd(&g_mdone[m], 0) < 16) __nanosleep(128);
            }
        }
        __syncthreads();
        const int b0 = steal[1];
        if (b0 >= BATCH) break;
        __threadfence();   // acquire g_embs

        const int half = t >> 8;
        epi_row(b0 + half, smem + half * 16384, t & 255,
                X, table, nf, res, goalW, goalb,
                chgW, chgb, ccgW, ccgb, out);
        __syncthreads();
    }
}

// ---------------------------------------------------------------------------
extern "C" void kernel_launch(void* const* d_in, const int* in_sizes, int n_in,
                              void* d_out, int out_size) {
    const float* X     = (const float*)d_in[0];
    const float* table = (const float*)d_in[1];
    const float* nf    = (const float*)d_in[2];
    const float* res   = (const float*)d_in[3];
    const float* goalW = (const float*)d_in[4];
    const float* goalb = (const float*)d_in[5];
    const float* bookW = (const float*)d_in[6];
    const float* bookb = (const float*)d_in[7];
    const float* chW   = (const float*)d_in[8];
    const float* chb   = (const float*)d_in[9];
    const float* ccW   = (const float*)d_in[10];
    const float* ccb   = (const float*)d_in[11];
    const float* chgW  = (const float*)d_in[12];
    const float* chgb  = (const float*)d_in[13];
    const float* ccgW  = (const float*)d_in[14];
    const float* ccgb  = (const float*)d_in[15];
    float* out = (float*)d_out;

    static bool attr_set = false;
    if (!attr_set) {
        cudaFuncSetAttribute(fused_kernel,
                             cudaFuncAttributeMaxDynamicSharedMemorySize, FSMEM);
        attr_set = true;
    }

    init_kernel<<<1, 256>>>(ccb, ccgW);

    fused_kernel<<<GRID, 512, FSMEM>>>(X, table, nf, res, goalW, goalb,
                                       bookb, chb, chgW, chgb, ccgW, ccgb,
                                       bookW, chW, ccW, out);
}

// round 16
// speedup vs baseline: 1.0130x; 1.0130x over previous
#include <cuda_runtime.h>
#include <cuda_bf16.h>
#include <math.h>
#include <stdint.h>

#define BATCH 4096
#define DIM   1024
#define NROWS 30

#define NGEMM  152            // CTAs that start on GEMM work (1/SM)
#define GRID   304            // 2 CTAs/SM x 152 SMs, one wave
#define NSTRM  (GRID - NGEMM) // streamer CTAs
#define NTILES 512            // 32 m-blocks x 16 n-blocks
#define FSMEM  (65536 + 128)  // GEMM A/B buffers + steal slots
#define NCHUNK 786432         // float8 chunks to convert (X, Wb, Wc)

// ---------------------------------------------------------------------------
// Scratch
// ---------------------------------------------------------------------------
__device__ __align__(16) float g_embs[(size_t)BATCH * 2048];
__device__ __align__(16) __nv_bfloat16 g_xbf[(size_t)BATCH * DIM];
__device__ __align__(16) __nv_bfloat16 g_wbf[(size_t)2048 * DIM];
__device__ __align__(16) float g_vcancel[DIM];
__device__ float g_scancel;
__device__ int g_tile_ctr;
__device__ int g_batch_ctr;
__device__ int g_mdone[32];
__device__ int g_conv_done;
__device__ int g_mv_done;

__device__ __forceinline__ float dot4(float4 a, float4 b) {
    return a.x * b.x + a.y * b.y + a.z * b.z + a.w * b.w;
}
__device__ __forceinline__ void cp16(uint32_t dst, const void* src) {
    asm volatile("cp.async.cg.shared.global [%0], [%1], 16;\n" :: "r"(dst), "l"(src));
}
__device__ __forceinline__ void cp_commit() {
    asm volatile("cp.async.commit_group;\n");
}
template <int N>
__device__ __forceinline__ void cp_wait() {
    asm volatile("cp.async.wait_group %0;\n" :: "n"(N));
}
__device__ __forceinline__ void ldmx4(uint32_t* r, uint32_t addr) {
    asm volatile("ldmatrix.sync.aligned.m8n8.x4.shared.b16 {%0,%1,%2,%3}, [%4];"
                 : "=r"(r[0]), "=r"(r[1]), "=r"(r[2]), "=r"(r[3]) : "r"(addr));
}
#define MMA_BF16(C, A, B0, B1)                                                 \
    asm volatile(                                                              \
        "mma.sync.aligned.m16n8k16.row.col.f32.bf16.bf16.f32 "                 \
        "{%0,%1,%2,%3}, {%4,%5,%6,%7}, {%8,%9}, {%0,%1,%2,%3};"                \
        : "+f"((C)[0]), "+f"((C)[1]), "+f"((C)[2]), "+f"((C)[3])               \
        : "r"((A)[0]), "r"((A)[1]), "r"((A)[2]), "r"((A)[3]),                  \
          "r"(B0), "r"(B1))

// ---------------------------------------------------------------------------
// Kernel 0: init counters + zero g_vcancel + compute g_scancel.  1 x 256.
// ---------------------------------------------------------------------------
__global__ void init_kernel(const float* __restrict__ cb,
                            const float* __restrict__ gw) {
    __shared__ float red[8];
    const int t = threadIdx.x, w = t >> 5, l = t & 31;
    ((float4*)g_vcancel)[t] = make_float4(0.f, 0.f, 0.f, 0.f);
    if (t < 32) g_mdone[t] = 0;
    if (t == 32) g_tile_ctr = 0;
    if (t == 33) g_batch_ctr = 0;
    if (t == 34) g_conv_done = 0;
    if (t == 35) g_mv_done = 0;
    float4 c = ((const float4*)cb)[t];
    float4 g = ((const float4*)gw)[t];
    float p = dot4(c, g);
    #pragma unroll
    for (int o = 16; o > 0; o >>= 1) p += __shfl_down_sync(0xffffffffu, p, o);
    if (l == 0) red[w] = p;
    __syncthreads();
    if (t == 0) {
        float s = 0.f;
        #pragma unroll
        for (int j = 0; j < 8; j++) s += red[j];
        g_scancel = s;
    }
}

// ---------------------------------------------------------------------------
// GEMM tile, 512 threads, warp tile 32x32 (R9/R10 version, 64 regs).
// ---------------------------------------------------------------------------
__device__ __forceinline__ void gemm_tile(int m0, int n0,
                                          uint32_t baseA, uint32_t baseB,
                                          const float* __restrict__ bb,
                                          const float* __restrict__ bch) {
    const int t = threadIdx.x;
    const int warp = t >> 5, lane = t & 31;
    const int wm = warp >> 2, wn = warp & 3;
    const int g = lane >> 2, tg = lane & 3;
    const int q = lane >> 3, r8 = lane & 7;
    const int qm = (q & 1) * 8 + r8;
    const int qk = (q >> 1) * 8;

    float acc[2][4][4];
    #pragma unroll
    for (int mt = 0; mt < 2; mt++)
        #pragma unroll
        for (int nt = 0; nt < 4; nt++)
            #pragma unroll
            for (int j = 0; j < 4; j++) acc[mt][nt][j] = 0.f;

    int lm[2], lc[2];
    #pragma unroll
    for (int i = 0; i < 2; i++) {
        int chunk = t + 512 * i;
        lm[i] = chunk >> 3;
        lc[i] = chunk & 7;
    }

    auto issue = [&](int s) {
        const int kb = s * 64;
        const uint32_t bo = (s & 1) * 16384;
        #pragma unroll
        for (int i = 0; i < 2; i++) {
            const int m = lm[i], c = lc[i];
            const int pc = c ^ (m & 7);
            cp16(baseA + bo + m * 128 + pc * 16,
                 g_xbf + (size_t)(m0 + m) * DIM + kb + c * 8);
            cp16(baseB + bo + m * 128 + pc * 16,
                 g_wbf + (size_t)(n0 + m) * DIM + kb + c * 8);
        }
        cp_commit();
    };

    issue(0);

    for (int s = 0; s < 16; s++) {
        __syncthreads();
        if (s < 15) { issue(s + 1); cp_wait<1>(); }
        else        { cp_wait<0>(); }
        __syncthreads();

        const uint32_t bo = (s & 1) * 16384;
        #pragma unroll
        for (int ks = 0; ks < 4; ks++) {
            const int kc = ks * 16 + qk;
            uint32_t af[2][4];
            #pragma unroll
            for (int mt = 0; mt < 2; mt++) {
                const int m = wm * 32 + mt * 16 + qm;
                ldmx4(af[mt], baseA + bo + m * 128 + (((kc >> 3) ^ (m & 7)) * 16));
            }
            uint32_t b0[4], b1[4];
            #pragma unroll
            for (int ntp = 0; ntp < 2; ntp++) {
                const int n = wn * 32 + ntp * 16 + qm;
                uint32_t r[4];
                ldmx4(r, baseB + bo + n * 128 + (((kc >> 3) ^ (n & 7)) * 16));
                b0[2 * ntp] = r[0]; b0[2 * ntp + 1] = r[1];
                b1[2 * ntp] = r[2]; b1[2 * ntp + 1] = r[3];
            }
            #pragma unroll
            for (int mt = 0; mt < 2; mt++)
                #pragma unroll
                for (int nt = 0; nt < 4; nt++)
                    MMA_BF16(acc[mt][nt], af[mt], b0[nt], b1[nt]);
        }
    }

    const float* bsel = (n0 < 1024) ? (bb + n0) : (bch + (n0 - 1024));
    #pragma unroll
    for (int mt = 0; mt < 2; mt++) {
        #pragma unroll
        for (int nt = 0; nt < 4; nt++) {
            const int row = m0 + wm * 32 + mt * 16 + g;
            const int col = wn * 32 + nt * 8 + 2 * tg;
            const float c0 = bsel[col], c1 = bsel[col + 1];
            float2 v01 = make_float2(acc[mt][nt][0] + c0, acc[mt][nt][1] + c1);
            float2 v23 = make_float2(acc[mt][nt][2] + c0, acc[mt][nt][3] + c1);
            *(float2*)&g_embs[(size_t)row * 2048 + n0 + col] = v01;
            *(float2*)&g_embs[(size_t)(row + 8) * 2048 + n0 + col] = v23;
        }
    }
}

// ---------------------------------------------------------------------------
// Epilogue body for one batch row, executed by a 256-thread half (t in 0..255)
// with its own smem bank `sm`. Embeddings in SMEM, ONE row per warp (measured
// optimum; wider variants hit the register cliff).
// ---------------------------------------------------------------------------
__device__ __forceinline__ void epi_row(
        int b, char* sm, int t,
        const float* __restrict__ X, const float* __restrict__ table,
        const float* __restrict__ nf, const float* __restrict__ res,
        const float* __restrict__ goalW, const float* __restrict__ goalb,
        const float* __restrict__ chgW, const float* __restrict__ chgb,
        const float* __restrict__ ccgW, const float* __restrict__ ccgb,
        float* __restrict__ out) {
    const int w = t >> 5, l = t & 31;

    float4* sbe = (float4*)sm;
    float4* sce = (float4*)(sm + 4096);
    float (*red)[9] = (float(*)[9])(sm + 8192);
    float* sdots = (float*)(sm + 8480);
    float* slb = (float*)(sm + 8516);
    float* slc = (float*)(sm + 8644);
    float* spb = (float*)(sm + 8772);
    float* spc = (float*)(sm + 8900);
    float* sc  = (float*)(sm + 9028);

    const float* be  = g_embs + (size_t)b * 2048;
    const float* ce  = be + 1024;
    const float* xb  = X   + (size_t)b * DIM;
    const float* nfb = nf  + (size_t)b * DIM;
    const float* rb  = res + (size_t)b * DIM;

    // ---- phase 1: nine 1024-length dots + stage embs to smem ----
    float p[9];
    {
        const int i0 = t * 4;
        float4 bv = *(const float4*)(be + i0);
        float4 cv = *(const float4*)(ce + i0);
        sbe[t] = bv;
        sce[t] = cv;
        float4 xv = *(const float4*)(xb + i0);
        float4 nv = *(const float4*)(nfb + i0);
        float4 rv = *(const float4*)(rb + i0);
        float4 g0 = *(const float4*)(goalW + i0);
        float4 g1 = *(const float4*)(goalW + 1024 + i0);
        float4 g2 = *(const float4*)(goalW + 2048 + i0);
        float4 cl = *(const float4*)(chgW + i0);
        float4 ch = *(const float4*)(chgW + 1024 + i0);
        float4 kh = *(const float4*)(ccgW + 1024 + i0);
        float4 vc = *(const float4*)(g_vcancel + i0);
        p[0] = dot4(bv, nv);
        p[1] = dot4(cv, nv);
        p[2] = dot4(cv, cl);
        p[3] = dot4(rv, ch);
        p[4] = dot4(xv, vc);
        p[5] = dot4(rv, kh);
        p[6] = dot4(xv, g0);
        p[7] = dot4(xv, g1);
        p[8] = dot4(xv, g2);
    }
    #pragma unroll
    for (int j = 0; j < 9; j++) {
        #pragma unroll
        for (int o = 16; o > 0; o >>= 1)
            p[j] += __shfl_down_sync(0xffffffffu, p[j], o);
    }
    if (l == 0) {
        #pragma unroll
        for (int j = 0; j < 9; j++) red[w][j] = p[j];
    }
    __syncthreads();
    if (t < 9) {
        float s = 0.f;
        #pragma unroll
        for (int ww = 0; ww < 8; ww++) s += red[ww][t];
        sdots[t] = s;
    }

    // ---- phase 2: table logits, 1 row per warp, dual dot ----
    for (int r = w; r < NROWS; r += 8) {
        const float4* t4 = (const float4*)(table + ((size_t)b * NROWS + r) * DIM);
        float ab = 0.f, ac = 0.f;
        #pragma unroll
        for (int j = 0; j < 8; j++) {
            float4 tv = t4[j * 32 + l];
            ab += dot4(tv, sbe[j * 32 + l]);
            ac += dot4(tv, sce[j * 32 + l]);
        }
        #pragma unroll
        for (int o = 16; o > 0; o >>= 1) {
            ab += __shfl_down_sync(0xffffffffu, ab, o);
            ac += __shfl_down_sync(0xffffffffu, ac, o);
        }
        if (l == 0) {
            slb[r + 1] = ab * 0.03125f;
            slc[r + 1] = ac * 0.03125f;
        }
    }
    __syncthreads();

    // ---- phase 3a: scalars ----
    if (t == 0) {
        slb[0] = sdots[0] * 0.03125f;
        slc[0] = sdots[1] * 0.03125f;
        float l0 = sdots[6] + goalb[0];
        float l1 = sdots[7] + goalb[1];
        float l2 = sdots[8] + goalb[2];
        float mx = fmaxf(l0, fmaxf(l1, l2));
        float e0 = expf(l0 - mx), e1 = expf(l1 - mx), e2 = expf(l2 - mx);
        float inv = 1.f / (e0 + e1 + e2);
        float bg = e0 * inv, chg = e1 * inv, cang = e2 * inv;
        float change_prob = 1.f / (1.f + expf(-(sdots[2] + sdots[3] + chgb[0])));
        float cancel_prob = 1.f / (1.f + expf(-(sdots[4] + sdots[5] + g_scancel + ccgb[0])));
        sc[0] = bg;
        sc[1] = chg * change_prob;
        sc[2] = cang * cancel_prob;
        sc[3] = cang * (1.f - cancel_prob) + chg * (1.f - change_prob);
    }
    __syncthreads();

    // ---- phase 3b: two 31-way softmaxes ----
    if (w < 2) {
        float* sl = w ? slc : slb;
        float* sp = w ? spc : spb;
        float v = (l < 31) ? sl[l] : -1e30f;
        float mx = v;
        #pragma unroll
        for (int o = 16; o > 0; o >>= 1)
            mx = fmaxf(mx, __shfl_xor_sync(0xffffffffu, mx, o));
        float e = (l < 31) ? expf(v - mx) : 0.f;
        float s = e;
        #pragma unroll
        for (int o = 16; o > 0; o >>= 1)
            s += __shfl_xor_sync(0xffffffffu, s, o);
        if (l < 31) sp[l] = e / s;
    }
    __syncthreads();

    // ---- phase 3c: final 63 outputs ----
    if (t < 63) {
        float o;
        if (t == 0)       o = sc[0] * spb[0] + sc[1] * spc[0];
        else if (t == 1)  o = sc[2];
        else if (t == 2)  o = sc[3];
        else if (t < 33)  o = sc[0] * spb[t - 2];
        else              o = sc[1] * spc[t - 32];
        out[(size_t)b * 63 + t] = o;
    }
}

// ---------------------------------------------------------------------------
// FUSED persistent kernel. 304 CTAs x 512 threads, 64KB smem, 2 CTAs/SM.
// GEMM CTAs (0..151): bf16 conv (barrier) -> tile stealing -> epilogue.
// Streamers (152..303): cancel matvec (barrier) -> epilogue.
// This is the measured optimum (R11: 160.5us) of the explored design space.
// ---------------------------------------------------------------------------
__global__ void __launch_bounds__(512, 2)
fused_kernel(const float* __restrict__ X, const float* __restrict__ table,
             const float* __restrict__ nf, const float* __restrict__ res,
             const float* __restrict__ goalW, const float* __restrict__ goalb,
             const float* __restrict__ bb, const float* __restrict__ bch,
             const float* __restrict__ chgW, const float* __restrict__ chgb,
             const float* __restrict__ ccgW, const float* __restrict__ ccgb,
             const float* __restrict__ Wb_f32, const float* __restrict__ Wc_f32,
             const float* __restrict__ ccW,
             float* __restrict__ out) {
    extern __shared__ char smem[];
    const uint32_t baseA = (uint32_t)__cvta_generic_to_shared(smem);
    const uint32_t baseB = baseA + 32768;
    volatile int* steal = (volatile int*)(smem + 65536);

    const int t = threadIdx.x;
    const int bid = blockIdx.x;

    if (bid < NGEMM) {
        // ---- folded conv_bf16: grid-stride over float8 chunks ----
        for (int c = bid * 512 + t; c < NCHUNK; c += NGEMM * 512) {
            const float* src;
            __nv_bfloat16* dst;
            size_t off;
            if (c < 524288)      { src = X;      dst = g_xbf;            off = (size_t)c * 8; }
            else if (c < 655360) { src = Wb_f32; dst = g_wbf;            off = (size_t)(c - 524288) * 8; }
            else                 { src = Wc_f32; dst = g_wbf + (1u<<20); off = (size_t)(c - 655360) * 8; }
            float4 a0 = *(const float4*)(src + off);
            float4 a1 = *(const float4*)(src + off + 4);
            __nv_bfloat162 h0 = __floats2bfloat162_rn(a0.x, a0.y);
            __nv_bfloat162 h1 = __floats2bfloat162_rn(a0.z, a0.w);
            __nv_bfloat162 h2 = __floats2bfloat162_rn(a1.x, a1.y);
            __nv_bfloat162 h3 = __floats2bfloat162_rn(a1.z, a1.w);
            uint4 o;
            o.x = *(uint32_t*)&h0; o.y = *(uint32_t*)&h1;
            o.z = *(uint32_t*)&h2; o.w = *(uint32_t*)&h3;
            *(uint4*)(dst + off) = o;
        }
        __threadfence();
        __syncthreads();
        if (t == 0) {
            atomicAdd(&g_conv_done, 1);
            while (atomicAdd(&g_conv_done, 0) < NGEMM) __nanosleep(64);
        }
        __syncthreads();

        // ---- GEMM tile stealing (m-major release) ----
        for (;;) {
            if (t == 0) steal[0] = atomicAdd(&g_tile_ctr, 1);
            __syncthreads();
            const int tile = steal[0];
            if (tile >= NTILES) break;
            const int m = tile >> 4, n = tile & 15;
            gemm_tile(m * 128, n * 128, baseA, baseB, bb, bch);
            __threadfence();
            __syncthreads();
            if (t == 0) atomicAdd(&g_mdone[m], 1);
        }
        __syncthreads();
        // need vcancel before joining the epilogue (streamers produce it)
        if (t == 0) {
            while (atomicAdd(&g_mv_done, 0) < NSTRM) __nanosleep(64);
        }
        __syncthreads();
        __threadfence();
    } else {
        // ---- folded matvec_cancel: 64 units of (512 k) x (32 i) ----
        const int e = bid - NGEMM;
        if (e < 64) {
            const int k  = (e & 1) * 512 + t;
            const int i0 = (e >> 1) * 32;
            float acc = 0.f;
            #pragma unroll
            for (int j = 0; j < 32; j++)
                acc += ccW[(size_t)(i0 + j) * DIM + k] * __ldg(ccgW + i0 + j);
            atomicAdd(&g_vcancel[k], acc);
        }
        __threadfence();
        __syncthreads();
        if (t == 0) {
            atomicAdd(&g_mv_done, 1);
            while (atomicAdd(&g_mv_done, 0) < NSTRM) __nanosleep(64);
        }
        __syncthreads();
        __threadfence();
    }

    // ---- epilogue phase: 2 rows per iteration (halves) ----
    for (;;) {
        if (t == 0) {
            int b0 = atomicAdd(&g_batch_ctr, 2);
            steal[1] = b0;
            if (b0 < BATCH) {
                const int m = b0 >> 7;
                while (atomicAdd(&g_mdone[m], 0) < 16) __nanosleep(128);
            }
        }
        __syncthreads();
        const int b0 = steal[1];
        if (b0 >= BATCH) break;
        __threadfence();   // acquire g_embs

        const int half = t >> 8;
        epi_row(b0 + half, smem + half * 16384, t & 255,
                X, table, nf, res, goalW, goalb,
                chgW, chgb, ccgW, ccgb, out);
        __syncthreads();
    }
}

// ---------------------------------------------------------------------------
extern "C" void kernel_launch(void* const* d_in, const int* in_sizes, int n_in,
                              void* d_out, int out_size) {
    const float* X     = (const float*)d_in[0];
    const float* table = (const float*)d_in[1];
    const float* nf    = (const float*)d_in[2];
    const float* res   = (const float*)d_in[3];
    const float* goalW = (const float*)d_in[4];
    const float* goalb = (const float*)d_in[5];
    const float* bookW = (const float*)d_in[6];
    const float* bookb = (const float*)d_in[7];
    const float* chW   = (const float*)d_in[8];
    const float* chb   = (const float*)d_in[9];
    const float* ccW   = (const float*)d_in[10];
    const float* ccb   = (const float*)d_in[11];
    const float* chgW  = (const float*)d_in[12];
    const float* chgb  = (const float*)d_in[13];
    const float* ccgW  = (const float*)d_in[14];
    const float* ccgb  = (const float*)d_in[15];
    float* out = (float*)d_out;

    static bool attr_set = false;
    if (!attr_set) {
        cudaFuncSetAttribute(fused_kernel,
                             cudaFuncAttributeMaxDynamicSharedMemorySize, FSMEM);
        attr_set = true;
    }

    init_kernel<<<1, 256>>>(ccb, ccgW);

    fused_kernel<<<GRID, 512, FSMEM>>>(X, table, nf, res, goalW, goalb,
                                       bookb, chb, chgW, chgb, ccgW, ccgb,
                                       bookW, chW, ccW, out);
}

// round 17
// speedup vs baseline: 1.0277x; 1.0144x over previous
#include <cuda_runtime.h>
#include <cuda_bf16.h>
#include <math.h>
#include <stdint.h>

#define BATCH 4096
#define DIM   1024
#define NROWS 30

#define NGEMM  152            // CTAs that start on GEMM work (1/SM)
#define GRID   304            // 2 CTAs/SM x 152 SMs, one wave
#define NSTRM  (GRID - NGEMM) // streamer CTAs
#define NTILES 512            // 32 m-blocks x 16 n-blocks
#define FSMEM  (65536 + 128)  // GEMM A/B buffers + steal slots
#define NCHUNK 786432         // float8 chunks to convert (X, Wb, Wc)

// ---------------------------------------------------------------------------
// Scratch.  g_embs now bf16 (halves intermediate DRAM traffic).
// ---------------------------------------------------------------------------
__device__ __align__(16) __nv_bfloat16 g_embs[(size_t)BATCH * 2048];
__device__ __align__(16) __nv_bfloat16 g_xbf[(size_t)BATCH * DIM];
__device__ __align__(16) __nv_bfloat16 g_wbf[(size_t)2048 * DIM];
__device__ __align__(16) float g_vcancel[DIM];
__device__ float g_scancel;
__device__ int g_tile_ctr;
__device__ int g_batch_ctr;
__device__ int g_mdone[32];
__device__ int g_conv_done;
__device__ int g_mv_done;

__device__ __forceinline__ float dot4(float4 a, float4 b) {
    return a.x * b.x + a.y * b.y + a.z * b.z + a.w * b.w;
}
__device__ __forceinline__ void cp16(uint32_t dst, const void* src) {
    asm volatile("cp.async.cg.shared.global [%0], [%1], 16;\n" :: "r"(dst), "l"(src));
}
__device__ __forceinline__ void cp_commit() {
    asm volatile("cp.async.commit_group;\n");
}
template <int N>
__device__ __forceinline__ void cp_wait() {
    asm volatile("cp.async.wait_group %0;\n" :: "n"(N));
}
__device__ __forceinline__ void ldmx4(uint32_t* r, uint32_t addr) {
    asm volatile("ldmatrix.sync.aligned.m8n8.x4.shared.b16 {%0,%1,%2,%3}, [%4];"
                 : "=r"(r[0]), "=r"(r[1]), "=r"(r[2]), "=r"(r[3]) : "r"(addr));
}
#define MMA_BF16(C, A, B0, B1)                                                 \
    asm volatile(                                                              \
        "mma.sync.aligned.m16n8k16.row.col.f32.bf16.bf16.f32 "                 \
        "{%0,%1,%2,%3}, {%4,%5,%6,%7}, {%8,%9}, {%0,%1,%2,%3};"                \
        : "+f"((C)[0]), "+f"((C)[1]), "+f"((C)[2]), "+f"((C)[3])               \
        : "r"((A)[0]), "r"((A)[1]), "r"((A)[2]), "r"((A)[3]),                  \
          "r"(B0), "r"(B1))

// ---------------------------------------------------------------------------
// Kernel 0: init counters + zero g_vcancel + compute g_scancel.  1 x 256.
// ---------------------------------------------------------------------------
__global__ void init_kernel(const float* __restrict__ cb,
                            const float* __restrict__ gw) {
    __shared__ float red[8];
    const int t = threadIdx.x, w = t >> 5, l = t & 31;
    ((float4*)g_vcancel)[t] = make_float4(0.f, 0.f, 0.f, 0.f);
    if (t < 32) g_mdone[t] = 0;
    if (t == 32) g_tile_ctr = 0;
    if (t == 33) g_batch_ctr = 0;
    if (t == 34) g_conv_done = 0;
    if (t == 35) g_mv_done = 0;
    float4 c = ((const float4*)cb)[t];
    float4 g = ((const float4*)gw)[t];
    float p = dot4(c, g);
    #pragma unroll
    for (int o = 16; o > 0; o >>= 1) p += __shfl_down_sync(0xffffffffu, p, o);
    if (l == 0) red[w] = p;
    __syncthreads();
    if (t == 0) {
        float s = 0.f;
        #pragma unroll
        for (int j = 0; j < 8; j++) s += red[j];
        g_scancel = s;
    }
}

// ---------------------------------------------------------------------------
// GEMM tile, 512 threads, warp tile 32x32; bf16 output to g_embs.
// ---------------------------------------------------------------------------
__device__ __forceinline__ void gemm_tile(int m0, int n0,
                                          uint32_t baseA, uint32_t baseB,
                                          const float* __restrict__ bb,
                                          const float* __restrict__ bch) {
    const int t = threadIdx.x;
    const int warp = t >> 5, lane = t & 31;
    const int wm = warp >> 2, wn = warp & 3;
    const int g = lane >> 2, tg = lane & 3;
    const int q = lane >> 3, r8 = lane & 7;
    const int qm = (q & 1) * 8 + r8;
    const int qk = (q >> 1) * 8;

    float acc[2][4][4];
    #pragma unroll
    for (int mt = 0; mt < 2; mt++)
        #pragma unroll
        for (int nt = 0; nt < 4; nt++)
            #pragma unroll
            for (int j = 0; j < 4; j++) acc[mt][nt][j] = 0.f;

    int lm[2], lc[2];
    #pragma unroll
    for (int i = 0; i < 2; i++) {
        int chunk = t + 512 * i;
        lm[i] = chunk >> 3;
        lc[i] = chunk & 7;
    }

    auto issue = [&](int s) {
        const int kb = s * 64;
        const uint32_t bo = (s & 1) * 16384;
        #pragma unroll
        for (int i = 0; i < 2; i++) {
            const int m = lm[i], c = lc[i];
            const int pc = c ^ (m & 7);
            cp16(baseA + bo + m * 128 + pc * 16,
                 g_xbf + (size_t)(m0 + m) * DIM + kb + c * 8);
            cp16(baseB + bo + m * 128 + pc * 16,
                 g_wbf + (size_t)(n0 + m) * DIM + kb + c * 8);
        }
        cp_commit();
    };

    issue(0);

    for (int s = 0; s < 16; s++) {
        __syncthreads();
        if (s < 15) { issue(s + 1); cp_wait<1>(); }
        else        { cp_wait<0>(); }
        __syncthreads();

        const uint32_t bo = (s & 1) * 16384;
        #pragma unroll
        for (int ks = 0; ks < 4; ks++) {
            const int kc = ks * 16 + qk;
            uint32_t af[2][4];
            #pragma unroll
            for (int mt = 0; mt < 2; mt++) {
                const int m = wm * 32 + mt * 16 + qm;
                ldmx4(af[mt], baseA + bo + m * 128 + (((kc >> 3) ^ (m & 7)) * 16));
            }
            uint32_t b0[4], b1[4];
            #pragma unroll
            for (int ntp = 0; ntp < 2; ntp++) {
                const int n = wn * 32 + ntp * 16 + qm;
                uint32_t r[4];
                ldmx4(r, baseB + bo + n * 128 + (((kc >> 3) ^ (n & 7)) * 16));
                b0[2 * ntp] = r[0]; b0[2 * ntp + 1] = r[1];
                b1[2 * ntp] = r[2]; b1[2 * ntp + 1] = r[3];
            }
            #pragma unroll
            for (int mt = 0; mt < 2; mt++)
                #pragma unroll
                for (int nt = 0; nt < 4; nt++)
                    MMA_BF16(acc[mt][nt], af[mt], b0[nt], b1[nt]);
        }
    }

    const float* bsel = (n0 < 1024) ? (bb + n0) : (bch + (n0 - 1024));
    #pragma unroll
    for (int mt = 0; mt < 2; mt++) {
        #pragma unroll
        for (int nt = 0; nt < 4; nt++) {
            const int row = m0 + wm * 32 + mt * 16 + g;
            const int col = wn * 32 + nt * 8 + 2 * tg;
            const float c0 = bsel[col], c1 = bsel[col + 1];
            __nv_bfloat162 h01 = __floats2bfloat162_rn(acc[mt][nt][0] + c0,
                                                       acc[mt][nt][1] + c1);
            __nv_bfloat162 h23 = __floats2bfloat162_rn(acc[mt][nt][2] + c0,
                                                       acc[mt][nt][3] + c1);
            *(__nv_bfloat162*)&g_embs[(size_t)row * 2048 + n0 + col] = h01;
            *(__nv_bfloat162*)&g_embs[(size_t)(row + 8) * 2048 + n0 + col] = h23;
        }
    }
}

// ---------------------------------------------------------------------------
// Epilogue body for one batch row, executed by a 256-thread half (t in 0..255)
// with its own smem bank `sm`. Embeddings arrive bf16 from g_embs and are
// widened to fp32 in SMEM; everything downstream unchanged.
// ---------------------------------------------------------------------------
__device__ __forceinline__ void epi_row(
        int b, char* sm, int t,
        const float* __restrict__ X, const float* __restrict__ table,
        const float* __restrict__ nf, const float* __restrict__ res,
        const float* __restrict__ goalW, const float* __restrict__ goalb,
        const float* __restrict__ chgW, const float* __restrict__ chgb,
        const float* __restrict__ ccgW, const float* __restrict__ ccgb,
        float* __restrict__ out) {
    const int w = t >> 5, l = t & 31;

    float4* sbe = (float4*)sm;
    float4* sce = (float4*)(sm + 4096);
    float (*red)[9] = (float(*)[9])(sm + 8192);
    float* sdots = (float*)(sm + 8480);
    float* slb = (float*)(sm + 8516);
    float* slc = (float*)(sm + 8644);
    float* spb = (float*)(sm + 8772);
    float* spc = (float*)(sm + 8900);
    float* sc  = (float*)(sm + 9028);

    const __nv_bfloat16* be = g_embs + (size_t)b * 2048;
    const __nv_bfloat16* ce = be + 1024;
    const float* xb  = X   + (size_t)b * DIM;
    const float* nfb = nf  + (size_t)b * DIM;
    const float* rb  = res + (size_t)b * DIM;

    // ---- phase 1: nine 1024-length dots + stage (widened) embs to smem ----
    float p[9];
    {
        const int i0 = t * 4;
        uint2 bu = *(const uint2*)(be + i0);
        uint2 cu = *(const uint2*)(ce + i0);
        float2 b01 = __bfloat1622float2(*(__nv_bfloat162*)&bu.x);
        float2 b23 = __bfloat1622float2(*(__nv_bfloat162*)&bu.y);
        float2 c01 = __bfloat1622float2(*(__nv_bfloat162*)&cu.x);
        float2 c23 = __bfloat1622float2(*(__nv_bfloat162*)&cu.y);
        float4 bv = make_float4(b01.x, b01.y, b23.x, b23.y);
        float4 cv = make_float4(c01.x, c01.y, c23.x, c23.y);
        sbe[t] = bv;
        sce[t] = cv;
        float4 xv = *(const float4*)(xb + i0);
        float4 nv = *(const float4*)(nfb + i0);
        float4 rv = *(const float4*)(rb + i0);
        float4 g0 = *(const float4*)(goalW + i0);
        float4 g1 = *(const float4*)(goalW + 1024 + i0);
        float4 g2 = *(const float4*)(goalW + 2048 + i0);
        float4 cl = *(const float4*)(chgW + i0);
        float4 ch = *(const float4*)(chgW + 1024 + i0);
        float4 kh = *(const float4*)(ccgW + 1024 + i0);
        float4 vc = *(const float4*)(g_vcancel + i0);
        p[0] = dot4(bv, nv);
        p[1] = dot4(cv, nv);
        p[2] = dot4(cv, cl);
        p[3] = dot4(rv, ch);
        p[4] = dot4(xv, vc);
        p[5] = dot4(rv, kh);
        p[6] = dot4(xv, g0);
        p[7] = dot4(xv, g1);
        p[8] = dot4(xv, g2);
    }
    #pragma unroll
    for (int j = 0; j < 9; j++) {
        #pragma unroll
        for (int o = 16; o > 0; o >>= 1)
            p[j] += __shfl_down_sync(0xffffffffu, p[j], o);
    }
    if (l == 0) {
        #pragma unroll
        for (int j = 0; j < 9; j++) red[w][j] = p[j];
    }
    __syncthreads();
    if (t < 9) {
        float s = 0.f;
        #pragma unroll
        for (int ww = 0; ww < 8; ww++) s += red[ww][t];
        sdots[t] = s;
    }

    // ---- phase 2: table logits, 1 row per warp, dual dot ----
    for (int r = w; r < NROWS; r += 8) {
        const float4* t4 = (const float4*)(table + ((size_t)b * NROWS + r) * DIM);
        float ab = 0.f, ac = 0.f;
        #pragma unroll
        for (int j = 0; j < 8; j++) {
            float4 tv = t4[j * 32 + l];
            ab += dot4(tv, sbe[j * 32 + l]);
            ac += dot4(tv, sce[j * 32 + l]);
        }
        #pragma unroll
        for (int o = 16; o > 0; o >>= 1) {
            ab += __shfl_down_sync(0xffffffffu, ab, o);
            ac += __shfl_down_sync(0xffffffffu, ac, o);
        }
        if (l == 0) {
            slb[r + 1] = ab * 0.03125f;
            slc[r + 1] = ac * 0.03125f;
        }
    }
    __syncthreads();

    // ---- phase 3a: scalars ----
    if (t == 0) {
        slb[0] = sdots[0] * 0.03125f;
        slc[0] = sdots[1] * 0.03125f;
        float l0 = sdots[6] + goalb[0];
        float l1 = sdots[7] + goalb[1];
        float l2 = sdots[8] + goalb[2];
        float mx = fmaxf(l0, fmaxf(l1, l2));
        float e0 = expf(l0 - mx), e1 = expf(l1 - mx), e2 = expf(l2 - mx);
        float inv = 1.f / (e0 + e1 + e2);
        float bg = e0 * inv, chg = e1 * inv, cang = e2 * inv;
        float change_prob = 1.f / (1.f + expf(-(sdots[2] + sdots[3] + chgb[0])));
        float cancel_prob = 1.f / (1.f + expf(-(sdots[4] + sdots[5] + g_scancel + ccgb[0])));
        sc[0] = bg;
        sc[1] = chg * change_prob;
        sc[2] = cang * cancel_prob;
        sc[3] = cang * (1.f - cancel_prob) + chg * (1.f - change_prob);
    }
    __syncthreads();

    // ---- phase 3b: two 31-way softmaxes ----
    if (w < 2) {
        float* sl = w ? slc : slb;
        float* sp = w ? spc : spb;
        float v = (l < 31) ? sl[l] : -1e30f;
        float mx = v;
        #pragma unroll
        for (int o = 16; o > 0; o >>= 1)
            mx = fmaxf(mx, __shfl_xor_sync(0xffffffffu, mx, o));
        float e = (l < 31) ? expf(v - mx) : 0.f;
        float s = e;
        #pragma unroll
        for (int o = 16; o > 0; o >>= 1)
            s += __shfl_xor_sync(0xffffffffu, s, o);
        if (l < 31) sp[l] = e / s;
    }
    __syncthreads();

    // ---- phase 3c: final 63 outputs ----
    if (t < 63) {
        float o;
        if (t == 0)       o = sc[0] * spb[0] + sc[1] * spc[0];
        else if (t == 1)  o = sc[2];
        else if (t == 2)  o = sc[3];
        else if (t < 33)  o = sc[0] * spb[t - 2];
        else              o = sc[1] * spc[t - 32];
        out[(size_t)b * 63 + t] = o;
    }
}

// ---------------------------------------------------------------------------
// FUSED persistent kernel. 304 CTAs x 512 threads, 64KB smem, 2 CTAs/SM.
// GEMM CTAs (0..151): bf16 conv (barrier) -> tile stealing -> epilogue.
// Streamers (152..303): cancel matvec (barrier) -> epilogue.
// ---------------------------------------------------------------------------
__global__ void __launch_bounds__(512, 2)
fused_kernel(const float* __restrict__ X, const float* __restrict__ table,
             const float* __restrict__ nf, const float* __restrict__ res,
             const float* __restrict__ goalW, const float* __restrict__ goalb,
             const float* __restrict__ bb, const float* __restrict__ bch,
             const float* __restrict__ chgW, const float* __restrict__ chgb,
             const float* __restrict__ ccgW, const float* __restrict__ ccgb,
             const float* __restrict__ Wb_f32, const float* __restrict__ Wc_f32,
             const float* __restrict__ ccW,
             float* __restrict__ out) {
    extern __shared__ char smem[];
    const uint32_t baseA = (uint32_t)__cvta_generic_to_shared(smem);
    const uint32_t baseB = baseA + 32768;
    volatile int* steal = (volatile int*)(smem + 65536);

    const int t = threadIdx.x;
    const int bid = blockIdx.x;

    if (bid < NGEMM) {
        // ---- folded conv_bf16: grid-stride over float8 chunks ----
        for (int c = bid * 512 + t; c < NCHUNK; c += NGEMM * 512) {
            const float* src;
            __nv_bfloat16* dst;
            size_t off;
            if (c < 524288)      { src = X;      dst = g_xbf;            off = (size_t)c * 8; }
            else if (c < 655360) { src = Wb_f32; dst = g_wbf;            off = (size_t)(c - 524288) * 8; }
            else                 { src = Wc_f32; dst = g_wbf + (1u<<20); off = (size_t)(c - 655360) * 8; }
            float4 a0 = *(const float4*)(src + off);
            float4 a1 = *(const float4*)(src + off + 4);
            __nv_bfloat162 h0 = __floats2bfloat162_rn(a0.x, a0.y);
            __nv_bfloat162 h1 = __floats2bfloat162_rn(a0.z, a0.w);
            __nv_bfloat162 h2 = __floats2bfloat162_rn(a1.x, a1.y);
            __nv_bfloat162 h3 = __floats2bfloat162_rn(a1.z, a1.w);
            uint4 o;
            o.x = *(uint32_t*)&h0; o.y = *(uint32_t*)&h1;
            o.z = *(uint32_t*)&h2; o.w = *(uint32_t*)&h3;
            *(uint4*)(dst + off) = o;
        }
        __threadfence();
        __syncthreads();
        if (t == 0) {
            atomicAdd(&g_conv_done, 1);
            while (atomicAdd(&g_conv_done, 0) < NGEMM) __nanosleep(64);
        }
        __syncthreads();

        // ---- GEMM tile stealing (m-major release) ----
        for (;;) {
            if (t == 0) steal[0] = atomicAdd(&g_tile_ctr, 1);
            __syncthreads();
            const int tile = steal[0];
            if (tile >= NTILES) break;
            const int m = tile >> 4, n = tile & 15;
            gemm_tile(m * 128, n * 128, baseA, baseB, bb, bch);
            __threadfence();
            __syncthreads();
            if (t == 0) atomicAdd(&g_mdone[m], 1);
        }
        __syncthreads();
        // need vcancel before joining the epilogue (streamers produce it)
        if (t == 0) {
            while (atomicAdd(&g_mv_done, 0) < NSTRM) __nanosleep(64);
        }
        __syncthreads();
        __threadfence();
    } else {
        // ---- folded matvec_cancel: 64 units of (512 k) x (32 i) ----
        const int e = bid - NGEMM;
        if (e < 64) {
            const int k  = (e & 1) * 512 + t;
            const int i0 = (e >> 1) * 32;
            float acc = 0.f;
            #pragma unroll
            for (int j = 0; j < 32; j++)
                acc += ccW[(size_t)(i0 + j) * DIM + k] * __ldg(ccgW + i0 + j);
            atomicAdd(&g_vcancel[k], acc);
        }
        __threadfence();
        __syncthreads();
        if (t == 0) {
            atomicAdd(&g_mv_done, 1);
            while (atomicAdd(&g_mv_done, 0) < NSTRM) __nanosleep(64);
        }
        __syncthreads();
        __threadfence();
    }

    // ---- epilogue phase: 2 rows per iteration (halves) ----
    for (;;) {
        if (t == 0) {
            int b0 = atomicAdd(&g_batch_ctr, 2);
            steal[1] = b0;
            if (b0 < BATCH) {
                const int m = b0 >> 7;
                while (atomicAdd(&g_mdone[m], 0) < 16) __nanosleep(128);
            }
        }
        __syncthreads();
        const int b0 = steal[1];
        if (b0 >= BATCH) break;
        __threadfence();   // acquire g_embs

        const int half = t >> 8;
        epi_row(b0 + half, smem + half * 16384, t & 255,
                X, table, nf, res, goalW, goalb,
                chgW, chgb, ccgW, ccgb, out);
        __syncthreads();
    }
}

// ---------------------------------------------------------------------------
extern "C" void kernel_launch(void* const* d_in, const int* in_sizes, int n_in,
                              void* d_out, int out_size) {
    const float* X     = (const float*)d_in[0];
    const float* table = (const float*)d_in[1];
    const float* nf    = (const float*)d_in[2];
    const float* res   = (const float*)d_in[3];
    const float* goalW = (const float*)d_in[4];
    const float* goalb = (const float*)d_in[5];
    const float* bookW = (const float*)d_in[6];
    const float* bookb = (const float*)d_in[7];
    const float* chW   = (const float*)d_in[8];
    const float* chb   = (const float*)d_in[9];
    const float* ccW   = (const float*)d_in[10];
    const float* ccb   = (const float*)d_in[11];
    const float* chgW  = (const float*)d_in[12];
    const float* chgb  = (const float*)d_in[13];
    const float* ccgW  = (const float*)d_in[14];
    const float* ccgb  = (const float*)d_in[15];
    float* out = (float*)d_out;

    static bool attr_set = false;
    if (!attr_set) {
        cudaFuncSetAttribute(fused_kernel,
                             cudaFuncAttributeMaxDynamicSharedMemorySize, FSMEM);
        attr_set = true;
    }

    init_kernel<<<1, 256>>>(ccb, ccgW);

    fused_kernel<<<GRID, 512, FSMEM>>>(X, table, nf, res, goalW, goalb,
                                       bookb, chb, chgW, chgb, ccgW, ccgb,
                                       bookW, chW, ccW, out);
}